// round 9
// baseline (speedup 1.0000x reference)
#include <cuda_runtime.h>
#include <math.h>

#define VDIM 1024
#define MAXB 8
#define MAXT 256
#define MAXU 65
#define DPS  66          // padded row stride in shared (<=2-way bank conflict on diagonals)
#define R_LO 64          // sentinel rows below 0
#define R_HI 320         // highest row index used (tcap+ucap+1 <= 320)
#define NROWS (R_LO + R_HI + 1)   // 385
#define NEG_BIG (-1.0e30f)

// Scratch (allocation-free rule: __device__ globals). Values stored in LOG2 domain.
__device__ float g_lp_blank[MAXB * MAXT * MAXU];          // [b][t][u]   (log2)
__device__ float g_lp_label[MAXB * MAXT * (MAXU - 1)];    // [b][t][u]   (log2)
__device__ float g_loss[MAXB];

__device__ __forceinline__ float ex2f(float x) { float r; asm("ex2.approx.f32 %0,%1;" : "=f"(r) : "f"(x)); return r; }
__device__ __forceinline__ float lg2f(float x) { float r; asm("lg2.approx.f32 %0,%1;" : "=f"(r) : "f"(x)); return r; }

// log2-domain logaddexp: log2(2^x + 2^y)
__device__ __forceinline__ float l2add(float x, float y)
{
    float mx = fmaxf(x, y);
    float mn = fminf(x, y);
    return mx + lg2f(1.f + ex2f(mn - mx));
}

// ---------------------------------------------------------------------------
// Kernel 1: per-row log-softmax over V=1024, COMPACTED over the active set
// {(b,t,u): t < act_len[b], u <= label_len[b]}. Warp w handles compact index
// w; decode via per-batch counts (uniform per warp, from L2-cached lens).
// Active warps are contiguous -> full resident-warp load pool -> high DRAM SOL.
// ---------------------------------------------------------------------------
__global__ void __launch_bounds__(256) softmax_pick_kernel(
    const float* __restrict__ acts, const int* __restrict__ labels,
    const int* __restrict__ act_lens, const int* __restrict__ label_lens,
    int B, int T, int U)
{
    const float LOG2E = 1.44269504088896340736f;

    int gw   = (blockIdx.x * blockDim.x + threadIdx.x) >> 5;  // compact row index
    int lane = threadIdx.x & 31;

    // decode compact index -> (b,t,u)
    int rem = gw;
    int b = -1, t = 0, u = 0;
#pragma unroll
    for (int bb = 0; bb < MAXB; ++bb) {
        if (bb >= B) break;
        int cu  = __ldg(&label_lens[bb]) + 1;
        int cnt = __ldg(&act_lens[bb]) * cu;
        if (b < 0) {
            if (rem < cnt) { b = bb; t = rem / cu; u = rem - t * cu; }
            else rem -= cnt;
        }
    }
    if (b < 0) return;               // past the active set

    int rowIdx = (b * T + t) * U + u;
    const float4* row = reinterpret_cast<const float4*>(acts) + (size_t)rowIdx * (VDIM / 4);

    float4 v[8];
#pragma unroll
    for (int k = 0; k < 8; ++k)
        v[k] = row[lane + 32 * k];

    float m = -INFINITY;
#pragma unroll
    for (int k = 0; k < 8; ++k)
        m = fmaxf(m, fmaxf(fmaxf(v[k].x, v[k].y), fmaxf(v[k].z, v[k].w)));
#pragma unroll
    for (int o = 16; o > 0; o >>= 1)
        m = fmaxf(m, __shfl_xor_sync(0xffffffffu, m, o));

    float s = 0.f;
#pragma unroll
    for (int k = 0; k < 8; ++k) {
        s += __expf(v[k].x - m);
        s += __expf(v[k].y - m);
        s += __expf(v[k].z - m);
        s += __expf(v[k].w - m);
    }
#pragma unroll
    for (int o = 16; o > 0; o >>= 1)
        s += __shfl_xor_sync(0xffffffffu, s, o);

    float logZ = m + __logf(s);

    if (lane == 0)
        g_lp_blank[rowIdx] = (v[0].x - logZ) * LOG2E;

    if (u < U - 1) {
        int lbl = labels[b * (U - 1) + u];
        int q   = lbl >> 2;
        if (lane == (q & 31)) {
            int kq = q >> 5;
            int c  = lbl & 3;
#pragma unroll
            for (int k = 0; k < 8; ++k)
                if (k == kq) {
                    float4 w = v[k];
                    float  x = (c == 0) ? w.x : (c == 1) ? w.y : (c == 2) ? w.z : w.w;
                    g_lp_label[(b * T + t) * (U - 1) + u] = (x - logZ) * LOG2E;
                }
        }
    }
}

// ---------------------------------------------------------------------------
// Kernel 2: alpha wavefront DP, one block per batch; DP in warp 0.
// Smem arrays padded with sentinel rows on BOTH sides (rows -64..320) so the
// inner loop needs NO clamping: each of the 6 operand streams is one pointer
// advancing by DPS per diagonal (folded to LDS [Rp+imm] under unroll 4).
//   sb[r][u] = lpb(r-1,u) for r in [1,T]; all other rows = NEG_BIG.
//   sl[r][c] = lpl(r,c-1) for r in [0,T-1], c in [1,64]; col 0 & other rows = NEG_BIG.
// Sentinels make the unified recurrence handle t==0 / u==0 edges; out-of-range
// cells compute finite garbage that provably never reaches a valid cell.
// ---------------------------------------------------------------------------
extern __shared__ __align__(16) float smem2[];

__global__ void __launch_bounds__(256) alpha_kernel(
    const int* __restrict__ act_lens, const int* __restrict__ label_lens,
    int T, int U)
{
    const float LN2 = 0.69314718055994530942f;

    int b    = blockIdx.x;
    int tid  = threadIdx.x;
    int lane = tid & 31;
    int warp = tid >> 5;
    int U1   = U - 1;

    float* sbx = smem2 + R_LO * DPS;                 // index by signed row
    float* slx = smem2 + NROWS * DPS + R_LO * DPS;

    const float* gb = g_lp_blank + (size_t)b * T * U;
    const float* gl = g_lp_label + (size_t)b * T * U1;

    // preload: one warp per row; sentinel rows filled NEG_BIG, data rows from L2
    for (int r = warp - R_LO; r <= R_HI; r += 8) {
        float* dst = sbx + r * DPS;
        if (r >= 1 && r <= T) {
            const float* src = gb + (r - 1) * U;
            for (int u = lane; u < U; u += 32) dst[u] = src[u];
        } else {
            for (int u = lane; u < U; u += 32) dst[u] = NEG_BIG;
        }
    }
    for (int r = warp - R_LO; r <= R_HI; r += 8) {
        float* dst = slx + r * DPS;
        if (r >= 0 && r < T) {
            if (lane == 0) dst[0] = NEG_BIG;
            for (int c = lane; c < U1; c += 32) dst[1 + c] = gl[r * U1 + c];
        } else {
            for (int u = lane; u < U; u += 32) dst[u] = NEG_BIG;
        }
    }

    int tcap = act_lens[b] - 1;
    int ucap = label_lens[b];
    __syncthreads();

    if (tid >= 32) return;

    int l  = tid;
    int u0 = 2 * l, u1 = 2 * l + 1;          // lane 31 also owns u=64 (slot 2)

    float a0 = 0.f, a1 = 0.f, a2 = 0.f;      // alpha at current diagonal (log2)
    float r0 = 0.f, r1 = 0.f, r2 = 0.f;      // captured alpha(tcap, u)

    int d0cap = tcap + u0;
    int d1cap = tcap + u1;
    int d2cap = tcap + 64;
    int D     = tcap + ucap;                 // last diagonal needed

    // six linear operand streams: row (d - u), column u; at d the pointers
    // point at this diagonal's operands, prefetch reads [DPS] = next diagonal
    const float* pb0 = sbx + (1 - u0) * DPS + u0;
    const float* pl0 = slx + (1 - u0) * DPS + u0;
    const float* pb1 = sbx + (1 - u1) * DPS + u1;
    const float* pl1 = slx + (1 - u1) * DPS + u1;
    const float* pb2 = sbx + (1 - 64) * DPS + 64;
    const float* pl2 = slx + (1 - 64) * DPS + 64;

    float vb0 = pb0[0], vl0 = pl0[0];
    float vb1 = pb1[0], vl1 = pl1[0];
    float vb2 = pb2[0], vl2 = pl2[0];

#pragma unroll 4
    for (int d = 1; d <= D; ++d) {
        float nvb0 = pb0[DPS], nvl0 = pl0[DPS];
        float nvb1 = pb1[DPS], nvl1 = pl1[DPS];
        float nvb2 = pb2[DPS], nvl2 = pl2[DPS];
        pb0 += DPS; pl0 += DPS; pb1 += DPS; pl1 += DPS; pb2 += DPS; pl2 += DPS;

        float p = __shfl_up_sync(0xffffffffu, a1, 1);   // alpha(.., u0-1) from lane l-1

        float n0 = l2add(a0 + vb0, p  + vl0);
        float n1 = l2add(a1 + vb1, a0 + vl1);
        float n2 = l2add(a2 + vb2, a1 + vl2);

        r0 = (d == d0cap) ? n0 : r0;
        r1 = (d == d1cap) ? n1 : r1;
        r2 = (d == d2cap) ? n2 : r2;

        a0 = n0; a1 = n1; a2 = n2;
        vb0 = nvb0; vl0 = nvl0; vb1 = nvb1; vl1 = nvl1; vb2 = nvb2; vl2 = nvl2;
    }

    // exactly one (lane, slot) owns (tcap, ucap)
    float res = 0.f; int hit = 0;
    if (u0 == ucap)                  { res = r0; hit = 1; }
    else if (u1 == ucap)             { res = r1; hit = 1; }
    else if (l == 31 && ucap == 64)  { res = r2; hit = 1; }
    if (hit)
        g_loss[b] = -(res + sbx[(tcap + 1) * DPS + ucap]) * LN2;
}

// ---------------------------------------------------------------------------
// Kernel 3: mean of per-batch costs -> d_out[0]
// ---------------------------------------------------------------------------
__global__ void finalize_kernel(float* __restrict__ out, int B)
{
    int lane = threadIdx.x;
    float v = (lane < B) ? g_loss[lane] : 0.f;
#pragma unroll
    for (int o = 16; o > 0; o >>= 1)
        v += __shfl_xor_sync(0xffffffffu, v, o);
    if (lane == 0)
        out[0] = v / (float)B;
}

// ---------------------------------------------------------------------------
extern "C" void kernel_launch(void* const* d_in, const int* in_sizes, int n_in,
                              void* d_out, int out_size)
{
    const float* acts       = (const float*)d_in[0];
    const int*   labels     = (const int*)d_in[1];
    const int*   act_lens   = (const int*)d_in[2];
    const int*   label_lens = (const int*)d_in[3];

    int B  = in_sizes[2];                 // 8
    int U1 = in_sizes[1] / B;             // 64
    int U  = U1 + 1;                      // 65
    long long total = in_sizes[0];
    int T  = (int)(total / ((long long)B * U * VDIM));   // 256

    // upper-bound grid; warps past the compacted active set exit immediately
    int nRows = B * T * U;
    int blocks = (nRows + 7) / 8;
    softmax_pick_kernel<<<blocks, 256>>>(acts, labels, act_lens, label_lens,
                                         B, T, U);

    int smemBytes = 2 * NROWS * DPS * (int)sizeof(float);   // 203,280 B
    cudaFuncSetAttribute(alpha_kernel,
                         cudaFuncAttributeMaxDynamicSharedMemorySize, smemBytes);
    alpha_kernel<<<B, 256, smemBytes>>>(act_lens, label_lens, T, U);

    finalize_kernel<<<1, 32>>>((float*)d_out, B);
}